// round 5
// baseline (speedup 1.0000x reference)
#include <cuda_runtime.h>
#include <cuda_bf16.h>

// Problem constants
#define B_  16
#define C_  4096
#define HD_ 1024   // H*D
#define F_  1024

// Tiling: grid = (NF, NK), block = TFX threads, one f-column per thread
#define NF  8
#define TFX 128
#define NK  16
#define TK  64

// Split-K partials (distinct slots, plain stores) + per-f-tile arrival count.
__device__ float        g_part[NK][B_][F_];   // 1 MB scratch
__device__ unsigned int g_cnt[NF];            // zero-init; finisher resets

__device__ __forceinline__ float ldcg_f(const float* p) {
    float v;
    asm volatile("ld.global.cg.f32 %0, [%1];" : "=f"(v) : "l"(p));
    return v;
}

// ---------------------------------------------------------------------------
// Single fused kernel. Attention degenerates (T=1 causal => softmax one-hot
// at rotated position 0) to v_sel[b] = bf16(kv_value[b, start_b]) -- or the
// fresh x@wv+bv row iff idx==0. y = v_sel @ wo + bo via split-K:
// block (fx,kx) computes g_part[kx][:, f-tile]; the LAST block to arrive on
// f-tile fx reduces the NK partials, adds bias, writes y, resets the counter.
// ---------------------------------------------------------------------------
__global__ void __launch_bounds__(TFX)
fused_kernel(const float* __restrict__ x,
             const int*   __restrict__ kv_idx,
             const float* __restrict__ kv_value,
             const float* __restrict__ wv,
             const float* __restrict__ bv,
             const float* __restrict__ wo,
             const float* __restrict__ bo,
             float* __restrict__ y)
{
    const int fx  = blockIdx.x;
    const int kx  = blockIdx.y;
    const int tid = threadIdx.x;
    const int k0  = kx * TK;
    const int f   = fx * TFX + tid;

    __shared__ float vs[B_][TK];
    __shared__ int   s_start[B_];
    __shared__ int   s_new[B_];

    if (tid < B_) {
        const int idx     = kv_idx[tid];
        const int new_idx = idx + 1;
        const int start   = (new_idx <= C_) ? 0 : (new_idx % C_);
        s_start[tid] = start;
        s_new[tid]   = (start == (idx % C_));   // only when idx == 0
    }
    __syncthreads();

    // Gather vs[b][k]: 1024 elems / 128 threads = 8 independent loads each
    #pragma unroll
    for (int i = tid; i < B_ * TK; i += TFX) {
        const int b = i / TK, k = i % TK;
        if (!s_new[b]) {
            const float v = __ldg(
                &kv_value[((size_t)b * C_ + s_start[b]) * HD_ + k0 + k]);
            vs[b][k] = __bfloat162float(__float2bfloat16(v));
        }
    }
    // Rare fallback (idx==0): fresh row = x[b] @ wv + bv for this k-slice
    for (int b = 0; b < B_; b++) {
        if (s_new[b] && tid < TK) {
            const int j = k0 + tid;
            float acc = bv[j];
            for (int ff = 0; ff < F_; ff++)
                acc = fmaf(__ldg(&x[b * F_ + ff]),
                           __ldg(&wv[(size_t)ff * HD_ + j]), acc);
            vs[b][tid] = __bfloat162float(__float2bfloat16(acc));
        }
    }
    __syncthreads();

    float acc[B_];
    #pragma unroll
    for (int b = 0; b < B_; b++) acc[b] = 0.0f;

    // Main loop: 4 k's per iter; wo straight from global (coalesced),
    // vs via LDS.128 broadcast. 16 independent FMA chains per thread.
    #pragma unroll
    for (int k4 = 0; k4 < TK; k4 += 4) {
        const float w0 = __ldg(&wo[(size_t)(k0 + k4 + 0) * F_ + f]);
        const float w1 = __ldg(&wo[(size_t)(k0 + k4 + 1) * F_ + f]);
        const float w2 = __ldg(&wo[(size_t)(k0 + k4 + 2) * F_ + f]);
        const float w3 = __ldg(&wo[(size_t)(k0 + k4 + 3) * F_ + f]);
        #pragma unroll
        for (int b = 0; b < B_; b++) {
            const float4 v = *reinterpret_cast<const float4*>(&vs[b][k4]);
            acc[b] = fmaf(v.x, w0,
                     fmaf(v.y, w1,
                     fmaf(v.z, w2,
                     fmaf(v.w, w3, acc[b]))));
        }
    }

    // Coalesced partial stores to distinct slots (no accumulation atomics)
    #pragma unroll
    for (int b = 0; b < B_; b++)
        g_part[kx][b][f] = acc[b];

    __threadfence();              // release: partials visible device-wide
    __syncthreads();              // whole block has fenced

    __shared__ int s_last;
    if (tid == 0)
        s_last = (atomicAdd(&g_cnt[fx], 1u) == (NK - 1));
    __syncthreads();

    if (s_last) {
        __threadfence();          // acquire: observe all producers' stores
        const float bias = __ldg(&bo[f]);
        #pragma unroll
        for (int b = 0; b < B_; b++) {
            float s0 = 0.f, s1 = 0.f, s2 = 0.f, s3 = 0.f;
            #pragma unroll
            for (int j = 0; j < NK; j += 4) {
                s0 += ldcg_f(&g_part[j + 0][b][f]);
                s1 += ldcg_f(&g_part[j + 1][b][f]);
                s2 += ldcg_f(&g_part[j + 2][b][f]);
                s3 += ldcg_f(&g_part[j + 3][b][f]);
            }
            y[b * F_ + f] = bias + ((s0 + s1) + (s2 + s3));
        }
        if (tid == 0) atomicExch(&g_cnt[fx], 0u);   // reset for next replay
    }
}

// ---------------------------------------------------------------------------
// Inputs (metadata order): x, mask, kv_idx, kv_key, kv_value,
//                          wq, bq, wk, bk, wv, bv, wo, bo
// ---------------------------------------------------------------------------
extern "C" void kernel_launch(void* const* d_in, const int* in_sizes, int n_in,
                              void* d_out, int out_size)
{
    const float* x        = (const float*)d_in[0];
    const int*   kv_idx   = (const int*)  d_in[2];
    const float* kv_value = (const float*)d_in[4];
    const float* wv       = (const float*)d_in[9];
    const float* bv       = (const float*)d_in[10];
    const float* wo       = (const float*)d_in[11];
    const float* bo       = (const float*)d_in[12];
    float* y = (float*)d_out;

    fused_kernel<<<dim3(NF, NK), TFX>>>(x, kv_idx, kv_value,
                                        wv, bv, wo, bo, y);
}

// round 6
// speedup vs baseline: 1.5837x; 1.5837x over previous
#include <cuda_runtime.h>
#include <cuda_bf16.h>

// Problem constants
#define B_  16
#define C_  4096
#define HD_ 1024   // H*D
#define F_  1024

// Tiling: grid = NF*NK = 128 blocks, 256 threads (128 f-lanes x 2 b-halves)
#define NF   8
#define TFX  128
#define NK   16
#define TK   64
#define BH   8
#define GRID (NF * NK)   // 128

// Split-K partials (distinct slots, plain stores) + monotonic arrival counter.
// Counter is never reset: each replay consumes exactly GRID arrivals, and each
// block waits for the next multiple of GRID -- replay-safe by construction.
__device__ float        g_part[NK][B_][F_];   // 1 MB scratch
__device__ unsigned int g_arrive;             // zero-init at module load

__device__ __forceinline__ float ldcg_f(const float* p) {
    float v;
    asm volatile("ld.global.cg.f32 %0, [%1];" : "=f"(v) : "l"(p));
    return v;
}
__device__ __forceinline__ unsigned ld_acq_u32(const unsigned* p) {
    unsigned v;
    asm volatile("ld.global.acquire.gpu.u32 %0, [%1];" : "=r"(v) : "l"(p));
    return v;
}

// ---------------------------------------------------------------------------
// Single kernel. Attention degenerates (T=1 causal => softmax one-hot at
// rotated position 0) to v_sel[b] = bf16(kv_value[b, start_b]) -- or the
// fresh x@wv+bv row iff idx==0. Then y = v_sel @ wo + bo.
// Phase 1: block (fx,kx) writes split-K partials g_part[kx][:, f-tile].
// Grid barrier (all 128 blocks co-resident; spin + nanosleep).
// Phase 2: every block reduces 128 distinct outputs in parallel.
// ---------------------------------------------------------------------------
__global__ void __launch_bounds__(2 * TFX)
fused_kernel(const float* __restrict__ x,
             const int*   __restrict__ kv_idx,
             const float* __restrict__ kv_value,
             const float* __restrict__ wv,
             const float* __restrict__ bv,
             const float* __restrict__ wo,
             const float* __restrict__ bo,
             float* __restrict__ y)
{
    const int fx   = blockIdx.x;
    const int kx   = blockIdx.y;
    const int bid  = kx * NF + fx;          // 0..127
    const int tid  = threadIdx.x;
    const int lane = tid & (TFX - 1);       // f within tile
    const int half = tid >> 7;              // 0 -> b[0,8), 1 -> b[8,16)
    const int b0   = half * BH;
    const int k0   = kx * TK;
    const int f    = fx * TFX + lane;

    __shared__ float vs[B_][TK];
    __shared__ int   s_start[B_];
    __shared__ int   s_new[B_];

    if (tid < B_) {
        const int idx     = kv_idx[tid];
        const int new_idx = idx + 1;
        const int start   = (new_idx <= C_) ? 0 : (new_idx % C_);
        s_start[tid] = start;
        s_new[tid]   = (start == (idx % C_));   // only when idx == 0
    }
    __syncthreads();

    // Gather vs[b][k]: 1024 elems / 256 threads = 4 independent loads each
    #pragma unroll
    for (int i = tid; i < B_ * TK; i += 2 * TFX) {
        const int b = i / TK, k = i % TK;
        if (!s_new[b]) {
            const float v = __ldg(
                &kv_value[((size_t)b * C_ + s_start[b]) * HD_ + k0 + k]);
            vs[b][k] = __bfloat162float(__float2bfloat16(v));
        }
    }
    // Rare fallback (idx==0): fresh row = x[b] @ wv + bv for this k-slice
    for (int b = 0; b < B_; b++) {
        if (s_new[b] && tid < TK) {
            const int j = k0 + tid;
            float acc = bv[j];
            for (int ff = 0; ff < F_; ff++)
                acc = fmaf(__ldg(&x[b * F_ + ff]),
                           __ldg(&wv[(size_t)ff * HD_ + j]), acc);
            vs[b][tid] = __bfloat162float(__float2bfloat16(acc));
        }
    }
    __syncthreads();

    // ---- Phase 1: partial GEMM for this (f-tile, k-chunk, b-half) ----
    float acc[BH];
    #pragma unroll
    for (int b = 0; b < BH; b++) acc[b] = 0.0f;

    #pragma unroll
    for (int k4 = 0; k4 < TK; k4 += 4) {
        const float w0 = __ldg(&wo[(size_t)(k0 + k4 + 0) * F_ + f]);
        const float w1 = __ldg(&wo[(size_t)(k0 + k4 + 1) * F_ + f]);
        const float w2 = __ldg(&wo[(size_t)(k0 + k4 + 2) * F_ + f]);
        const float w3 = __ldg(&wo[(size_t)(k0 + k4 + 3) * F_ + f]);
        #pragma unroll
        for (int b = 0; b < BH; b++) {
            const float4 v = *reinterpret_cast<const float4*>(&vs[b0 + b][k4]);
            acc[b] = fmaf(v.x, w0,
                     fmaf(v.y, w1,
                     fmaf(v.z, w2,
                     fmaf(v.w, w3, acc[b]))));
        }
    }

    #pragma unroll
    for (int b = 0; b < BH; b++)
        g_part[kx][b0 + b][f] = acc[b];

    // ---- Grid barrier: release partials, await all 128 blocks ----
    __threadfence();            // release our stores
    __syncthreads();            // whole block fenced

    __shared__ unsigned s_target;
    if (tid == 0) {
        const unsigned gen = atomicAdd(&g_arrive, 1u);
        s_target = (gen / GRID + 1u) * GRID;
    }
    __syncthreads();
    if (tid == 0) {
        while (ld_acq_u32(&g_arrive) < s_target)
            __nanosleep(64);
    }
    __syncthreads();            // all threads see barrier passed (acquire)

    // ---- Phase 2: distributed reduce. 128 outputs per block, 1/thread ----
    if (tid < 128) {
        const int idx = bid * 128 + tid;        // idx = b*F_ + f
        const int fb  = idx & (F_ - 1);
        const int bb  = idx >> 10;

        float s0 = __ldg(&bo[fb]), s1 = 0.f, s2 = 0.f, s3 = 0.f;
        #pragma unroll
        for (int j = 0; j < NK; j += 4) {
            s0 += ldcg_f(&g_part[j + 0][bb][fb]);
            s1 += ldcg_f(&g_part[j + 1][bb][fb]);
            s2 += ldcg_f(&g_part[j + 2][bb][fb]);
            s3 += ldcg_f(&g_part[j + 3][bb][fb]);
        }
        y[idx] = (s0 + s1) + (s2 + s3);
    }
}

// ---------------------------------------------------------------------------
// Inputs (metadata order): x, mask, kv_idx, kv_key, kv_value,
//                          wq, bq, wk, bk, wv, bv, wo, bo
// ---------------------------------------------------------------------------
extern "C" void kernel_launch(void* const* d_in, const int* in_sizes, int n_in,
                              void* d_out, int out_size)
{
    const float* x        = (const float*)d_in[0];
    const int*   kv_idx   = (const int*)  d_in[2];
    const float* kv_value = (const float*)d_in[4];
    const float* wv       = (const float*)d_in[9];
    const float* bv       = (const float*)d_in[10];
    const float* wo       = (const float*)d_in[11];
    const float* bo       = (const float*)d_in[12];
    float* y = (float*)d_out;

    fused_kernel<<<dim3(NF, NK), 2 * TFX>>>(x, kv_idx, kv_value,
                                            wv, bv, wo, bo, y);
}